// round 1
// baseline (speedup 1.0000x reference)
#include <cuda_runtime.h>
#include <cstdint>
#include <cstddef>

#define MEMB   8
#define BATCHI 4096
#define E_DIM  512
#define H_DIM  1024
#define V_DIM  4096
#define ROWS   (MEMB * BATCHI)   // 32768

// Scratch for the hidden activations (device global: allocation-free).
__device__ float g_h[(size_t)ROWS * H_DIM];

// ---------------------------------------------------------------------------
// helpers
// ---------------------------------------------------------------------------
__device__ __forceinline__ float tf32_rna(float x) {
    uint32_t u;
    asm("cvt.rna.tf32.f32 %0, %1;" : "=r"(u) : "f"(x));
    return __uint_as_float(u);
}

__device__ __forceinline__ void mma_tf32(float (&d)[4], const uint32_t (&a)[4],
                                         const uint32_t (&b)[2]) {
    asm volatile(
        "mma.sync.aligned.m16n8k8.row.col.f32.tf32.tf32.f32 "
        "{%0,%1,%2,%3}, {%4,%5,%6,%7}, {%8,%9}, {%0,%1,%2,%3};\n"
        : "+f"(d[0]), "+f"(d[1]), "+f"(d[2]), "+f"(d[3])
        : "r"(a[0]), "r"(a[1]), "r"(a[2]), "r"(a[3]), "r"(b[0]), "r"(b[1]));
}

// ---------------------------------------------------------------------------
// Grouped GEMM + bias:  C[row, n] = sum_k A[row, k] * W[m, k, n] + bias[m, n]
// row-tile picks member m = (row / 4096). Tiles: BM=128, BN=128, BK=16.
// 256 threads = 8 warps arranged 2(m) x 4(n); warp tile 64x32;
// per warp 4x4 m16n8k8 mma per 8-wide k-step.
// ---------------------------------------------------------------------------
__launch_bounds__(256)
__global__ void gemm_bias_tf32(const float* __restrict__ A,
                               const float* __restrict__ W,
                               const float* __restrict__ bias,
                               float* __restrict__ C,
                               int K, int N) {
    constexpr int BM = 128, BN = 128, BK = 16;
    constexpr int AST = 20;    // As row stride (floats): conflict-free frag loads
    constexpr int BST = 136;   // Bs row stride (floats): conflict-free frag loads

    __shared__ __align__(16) float As[2][BM * AST];
    __shared__ __align__(16) float Bs[2][BK * BST];

    const int tid  = threadIdx.x;
    const int lane = tid & 31;
    const int warp = tid >> 5;
    const int wm   = warp >> 2;      // 0..1
    const int wn   = warp & 3;       // 0..3
    const int g    = lane >> 2;      // groupID 0..7
    const int r    = lane & 3;       // thread-in-group 0..3

    const int brow   = blockIdx.y * BM;
    const int bcol   = blockIdx.x * BN;
    const int member = brow >> 12;   // / 4096
    const float* Wm  = W + (size_t)member * K * N;
    const float* bm  = bias + (size_t)member * N;

    float acc[4][4][4];
#pragma unroll
    for (int i = 0; i < 4; i++)
#pragma unroll
        for (int j = 0; j < 4; j++)
#pragma unroll
            for (int c = 0; c < 4; c++) acc[i][j][c] = 0.f;

    const int nkt = K / BK;
    float4 areg[2], breg[2];

    // ---- prologue: load k-tile 0 into buffer 0 ----
#pragma unroll
    for (int j = 0; j < 2; j++) {
        int idx = tid + j * 256;
        int arow = idx >> 2, akq = idx & 3;
        areg[j] = *(const float4*)(A + (size_t)(brow + arow) * K + akq * 4);
        int bk = idx >> 5, bn = idx & 31;
        breg[j] = *(const float4*)(Wm + (size_t)bk * N + bcol + bn * 4);
    }
#pragma unroll
    for (int j = 0; j < 2; j++) {
        int idx = tid + j * 256;
        int arow = idx >> 2, akq = idx & 3;
        float4 ta;
        ta.x = tf32_rna(areg[j].x); ta.y = tf32_rna(areg[j].y);
        ta.z = tf32_rna(areg[j].z); ta.w = tf32_rna(areg[j].w);
        *(float4*)&As[0][arow * AST + akq * 4] = ta;
        int bk = idx >> 5, bn = idx & 31;
        float4 tb;
        tb.x = tf32_rna(breg[j].x); tb.y = tf32_rna(breg[j].y);
        tb.z = tf32_rna(breg[j].z); tb.w = tf32_rna(breg[j].w);
        *(float4*)&Bs[0][bk * BST + bn * 4] = tb;
    }
    __syncthreads();

    for (int kt = 0; kt < nkt; kt++) {
        const int buf = kt & 1;
        const bool pf = (kt + 1 < nkt);

        if (pf) {
#pragma unroll
            for (int j = 0; j < 2; j++) {
                int idx = tid + j * 256;
                int arow = idx >> 2, akq = idx & 3;
                areg[j] = *(const float4*)(A + (size_t)(brow + arow) * K +
                                           (kt + 1) * BK + akq * 4);
                int bk = idx >> 5, bn = idx & 31;
                breg[j] = *(const float4*)(Wm + (size_t)((kt + 1) * BK + bk) * N +
                                           bcol + bn * 4);
            }
        }

        // ---- compute on current buffer ----
#pragma unroll
        for (int ks = 0; ks < 2; ks++) {
            uint32_t af[4][4];
            uint32_t bf[4][2];
#pragma unroll
            for (int mt = 0; mt < 4; mt++) {
                const float* ap =
                    &As[buf][(wm * 64 + mt * 16 + g) * AST + ks * 8 + r];
                af[mt][0] = __float_as_uint(ap[0]);
                af[mt][1] = __float_as_uint(ap[8 * AST]);
                af[mt][2] = __float_as_uint(ap[4]);
                af[mt][3] = __float_as_uint(ap[8 * AST + 4]);
            }
#pragma unroll
            for (int nt = 0; nt < 4; nt++) {
                const float* bp =
                    &Bs[buf][(ks * 8 + r) * BST + wn * 32 + nt * 8 + g];
                bf[nt][0] = __float_as_uint(bp[0]);
                bf[nt][1] = __float_as_uint(bp[4 * BST]);
            }
#pragma unroll
            for (int mt = 0; mt < 4; mt++)
#pragma unroll
                for (int nt = 0; nt < 4; nt++)
                    mma_tf32(acc[mt][nt], af[mt], bf[nt]);
        }

        if (pf) {
            const int nb = buf ^ 1;
#pragma unroll
            for (int j = 0; j < 2; j++) {
                int idx = tid + j * 256;
                int arow = idx >> 2, akq = idx & 3;
                float4 ta;
                ta.x = tf32_rna(areg[j].x); ta.y = tf32_rna(areg[j].y);
                ta.z = tf32_rna(areg[j].z); ta.w = tf32_rna(areg[j].w);
                *(float4*)&As[nb][arow * AST + akq * 4] = ta;
                int bk = idx >> 5, bn = idx & 31;
                float4 tb;
                tb.x = tf32_rna(breg[j].x); tb.y = tf32_rna(breg[j].y);
                tb.z = tf32_rna(breg[j].z); tb.w = tf32_rna(breg[j].w);
                *(float4*)&Bs[nb][bk * BST + bn * 4] = tb;
            }
        }
        __syncthreads();
    }

    // ---- epilogue: bias add + store ----
#pragma unroll
    for (int mt = 0; mt < 4; mt++) {
        const int row0 = brow + wm * 64 + mt * 16 + g;
#pragma unroll
        for (int nt = 0; nt < 4; nt++) {
            const int col0 = bcol + wn * 32 + nt * 8 + r * 2;
            const float bx0 = bm[col0];
            const float bx1 = bm[col0 + 1];
            float2 v0, v1;
            v0.x = acc[mt][nt][0] + bx0;
            v0.y = acc[mt][nt][1] + bx1;
            v1.x = acc[mt][nt][2] + bx0;
            v1.y = acc[mt][nt][3] + bx1;
            *(float2*)(C + (size_t)row0 * N + col0) = v0;
            *(float2*)(C + (size_t)(row0 + 8) * N + col0) = v1;
        }
    }
}

// ---------------------------------------------------------------------------
// Fused LayerNorm(+affine) + SiLU over g_h rows (H=1024). One CTA per row.
// ---------------------------------------------------------------------------
__launch_bounds__(256)
__global__ void ln_silu_kernel(const float* __restrict__ ln_w,
                               const float* __restrict__ ln_b) {
    const int row = blockIdx.x;
    const int m   = row >> 12;  // / 4096
    float* hp = g_h + (size_t)row * H_DIM;
    const int t = threadIdx.x;

    float4 x = *(const float4*)(hp + t * 4);
    float s = x.x + x.y + x.z + x.w;
    float q = x.x * x.x + x.y * x.y + x.z * x.z + x.w * x.w;

#pragma unroll
    for (int o = 16; o; o >>= 1) {
        s += __shfl_xor_sync(0xffffffffu, s, o);
        q += __shfl_xor_sync(0xffffffffu, q, o);
    }
    __shared__ float rs[8], rq[8];
    if ((t & 31) == 0) { rs[t >> 5] = s; rq[t >> 5] = q; }
    __syncthreads();
    s = rs[0] + rs[1] + rs[2] + rs[3] + rs[4] + rs[5] + rs[6] + rs[7];
    q = rq[0] + rq[1] + rq[2] + rq[3] + rq[4] + rq[5] + rq[6] + rq[7];

    const float mu  = s * (1.0f / H_DIM);
    const float var = q * (1.0f / H_DIM) - mu * mu;
    const float inv = rsqrtf(var + 1e-5f);

    const float4 w = *(const float4*)(ln_w + (size_t)m * H_DIM + t * 4);
    const float4 b = *(const float4*)(ln_b + (size_t)m * H_DIM + t * 4);

    float4 y;
    {
        float v;
        v = (x.x - mu) * inv * w.x + b.x; y.x = v / (1.f + __expf(-v));
        v = (x.y - mu) * inv * w.y + b.y; y.y = v / (1.f + __expf(-v));
        v = (x.z - mu) * inv * w.z + b.z; y.z = v / (1.f + __expf(-v));
        v = (x.w - mu) * inv * w.w + b.w; y.w = v / (1.f + __expf(-v));
    }
    *(float4*)(hp + t * 4) = y;
}

// ---------------------------------------------------------------------------
// launch
// ---------------------------------------------------------------------------
extern "C" void kernel_launch(void* const* d_in, const int* in_sizes, int n_in,
                              void* d_out, int out_size) {
    const float* x   = (const float*)d_in[0];  // [32768, 512]
    const float* W1  = (const float*)d_in[1];  // [8, 512, 1024]
    const float* b1  = (const float*)d_in[2];  // [8, 1024]
    const float* lw  = (const float*)d_in[3];  // [8, 1024]
    const float* lb  = (const float*)d_in[4];  // [8, 1024]
    const float* W2  = (const float*)d_in[5];  // [8, 1024, 4096]
    const float* b2  = (const float*)d_in[6];  // [8, 4096]
    float* out = (float*)d_out;                // [32768, 4096]

    float* h = nullptr;
    cudaGetSymbolAddress((void**)&h, g_h);

    dim3 blk(256);
    gemm_bias_tf32<<<dim3(H_DIM / 128, ROWS / 128), blk>>>(x, W1, b1, h,
                                                           E_DIM, H_DIM);
    ln_silu_kernel<<<ROWS, blk>>>(lw, lb);
    gemm_bias_tf32<<<dim3(V_DIM / 128, ROWS / 128), blk>>>(h, W2, b2, out,
                                                           H_DIM, V_DIM);
}

// round 3
// speedup vs baseline: 1.0887x; 1.0887x over previous
#include <cuda_runtime.h>
#include <cstdint>
#include <cstddef>

#define MEMB   8
#define BATCHI 4096
#define E_DIM  512
#define H_DIM  1024
#define V_DIM  4096
#define ROWS   (MEMB * BATCHI)   // 32768

// ---------------- scratch (device globals: allocation-free) ----------------
__device__ float g_xr [(size_t)ROWS * E_DIM];          // tf32-rounded x
__device__ float g_w1r[(size_t)MEMB * E_DIM * H_DIM];  // tf32-rounded W1
__device__ float g_w2r[(size_t)MEMB * H_DIM * V_DIM];  // tf32-rounded W2
__device__ float g_h  [(size_t)ROWS * H_DIM];          // hidden activations

// ---------------- helpers ----------------
__device__ __forceinline__ float tf32_rna(float x) {
    uint32_t u;
    asm("cvt.rna.tf32.f32 %0, %1;" : "=r"(u) : "f"(x));
    return __uint_as_float(u);
}
__device__ __forceinline__ uint32_t smem_u32(const void* p) {
    uint32_t a;
    asm("{ .reg .u64 t; cvta.to.shared.u64 t, %1; cvt.u32.u64 %0, t; }"
        : "=r"(a) : "l"(p));
    return a;
}
__device__ __forceinline__ void cp16(uint32_t s, const void* g) {
    asm volatile("cp.async.cg.shared.global [%0], [%1], 16;" :: "r"(s), "l"(g));
}
__device__ __forceinline__ void cp_commit() {
    asm volatile("cp.async.commit_group;" ::: "memory");
}
__device__ __forceinline__ void cp_wait2() {
    asm volatile("cp.async.wait_group 2;" ::: "memory");
}
__device__ __forceinline__ void mma_tf32(float (&d)[4], const uint32_t (&a)[4],
                                         const uint32_t (&b)[2]) {
    asm volatile(
        "mma.sync.aligned.m16n8k8.row.col.f32.tf32.tf32.f32 "
        "{%0,%1,%2,%3}, {%4,%5,%6,%7}, {%8,%9}, {%0,%1,%2,%3};\n"
        : "+f"(d[0]), "+f"(d[1]), "+f"(d[2]), "+f"(d[3])
        : "r"(a[0]), "r"(a[1]), "r"(a[2]), "r"(a[3]), "r"(b[0]), "r"(b[1]));
}

// ---------------- tiling ----------------
#define BM   128
#define BN   256
#define BK   16
#define STAGES 4
#define AST  20        // As row stride (floats), conflict-free
#define BST  264       // Bs row stride (floats), 264 mod 32 == 8 -> conflict-free
#define A_FLOATS (BM * AST)         // 2560
#define B_FLOATS (BK * BST)         // 4224
#define STAGE_FLOATS (A_FLOATS + B_FLOATS)   // 6784
#define STAGE_BYTES  (STAGE_FLOATS * 4)      // 27136
#define SMEM_TOTAL   (STAGES * STAGE_BYTES)  // 108544
#define A_CHUNKS (BM * BK / 4)      // 512 16B chunks
#define B_CHUNKS (BK * BN / 4)      // 1024

// issue one stage worth of cp.async (6 chunks / thread, 256 threads)
__device__ __forceinline__ void load_stage(uint32_t sbase_bytes, int st,
                                           const float* __restrict__ Ag,
                                           const float* __restrict__ Bg,
                                           int K, int Ntot, int tid) {
    const uint32_t sA = sbase_bytes + st * STAGE_BYTES;
    const uint32_t sB = sA + A_FLOATS * 4;
#pragma unroll
    for (int j = 0; j < (A_CHUNKS + B_CHUNKS) / 256; j++) {
        const int c = tid + j * 256;
        if (c < A_CHUNKS) {
            const int row = c >> 2, q = c & 3;      // 4 chunks per row (BK=16)
            cp16(sA + (uint32_t)(row * AST * 4 + q * 16),
                 Ag + (size_t)row * K + q * 4);
        } else {
            const int b = c - A_CHUNKS;
            const int k = b >> 6, q = b & 63;       // 64 chunks per k-row (BN=256)
            cp16(sB + (uint32_t)(k * BST * 4 + q * 16),
                 Bg + (size_t)k * Ntot + q * 4);
        }
    }
}

// ---------------- GEMM: C[row,n] = sum_k A[row,k]*W[m,k,n] + bias[m,n] ----------
// 256 threads = 8 warps (2m x 4n), warp tile 64x64, 4-stage cp.async pipeline.
__launch_bounds__(256, 1)
__global__ void gemm_mma(const float* __restrict__ A,
                         const float* __restrict__ W,
                         const float* __restrict__ bias,
                         float* __restrict__ C,
                         int K, int Ntot, int NT) {
    extern __shared__ __align__(16) float smf[];
    const uint32_t sbase = smem_u32(smf);

    const int tid  = threadIdx.x;
    const int lane = tid & 31;
    const int warp = tid >> 5;
    const int wm   = warp >> 2;      // 0..1
    const int wn   = warp & 3;       // 0..3
    const int g    = lane >> 2;      // 0..7
    const int r    = lane & 3;       // 0..3

    const int brow   = blockIdx.y * BM;
    const int bcol   = blockIdx.x * BN;
    const int member = brow >> 12;

    const float* Ag0 = A + (size_t)brow * K;
    const float* Bg0 = W + (size_t)member * K * Ntot + bcol;

    float acc[4][8][4];
#pragma unroll
    for (int i = 0; i < 4; i++)
#pragma unroll
        for (int j = 0; j < 8; j++)
#pragma unroll
            for (int c = 0; c < 4; c++) acc[i][j][c] = 0.f;

    // prologue: stages 0..2
#pragma unroll
    for (int s = 0; s < STAGES - 1; s++) {
        load_stage(sbase, s, Ag0 + s * BK, Bg0 + (size_t)s * BK * Ntot,
                   K, Ntot, tid);
        cp_commit();
    }

    for (int t = 0; t < NT; t++) {
        cp_wait2();
        __syncthreads();

        const int u = t + STAGES - 1;
        if (u < NT) {
            load_stage(sbase, u & (STAGES - 1), Ag0 + u * BK,
                       Bg0 + (size_t)u * BK * Ntot, K, Ntot, tid);
        }
        cp_commit();

        const float* As = smf + (t & (STAGES - 1)) * STAGE_FLOATS;
        const float* Bs = As + A_FLOATS;

#pragma unroll
        for (int ks = 0; ks < 2; ks++) {
            uint32_t af[4][4];
            uint32_t bf[8][2];
#pragma unroll
            for (int mt = 0; mt < 4; mt++) {
                const float* ap = &As[(wm * 64 + mt * 16 + g) * AST + ks * 8 + r];
                af[mt][0] = __float_as_uint(ap[0]);
                af[mt][1] = __float_as_uint(ap[8 * AST]);
                af[mt][2] = __float_as_uint(ap[4]);
                af[mt][3] = __float_as_uint(ap[8 * AST + 4]);
            }
#pragma unroll
            for (int nt = 0; nt < 8; nt++) {
                const float* bp = &Bs[(ks * 8 + r) * BST + wn * 64 + nt * 8 + g];
                bf[nt][0] = __float_as_uint(bp[0]);
                bf[nt][1] = __float_as_uint(bp[4 * BST]);
            }
#pragma unroll
            for (int mt = 0; mt < 4; mt++)
#pragma unroll
                for (int nt = 0; nt < 8; nt++)
                    mma_tf32(acc[mt][nt], af[mt], bf[nt]);
        }
    }

    // epilogue: bias + store
    const float* bm = bias + (size_t)member * Ntot + bcol;
#pragma unroll
    for (int mt = 0; mt < 4; mt++) {
        const int row0 = brow + wm * 64 + mt * 16 + g;
#pragma unroll
        for (int nt = 0; nt < 8; nt++) {
            const int col0 = bcol + wn * 64 + nt * 8 + r * 2;
            const float bx0 = __ldg(bm + (col0 - bcol));
            const float bx1 = __ldg(bm + (col0 - bcol) + 1);
            float2 v0, v1;
            v0.x = acc[mt][nt][0] + bx0;
            v0.y = acc[mt][nt][1] + bx1;
            v1.x = acc[mt][nt][2] + bx0;
            v1.y = acc[mt][nt][3] + bx1;
            *(float2*)(C + (size_t)row0 * Ntot + col0) = v0;
            *(float2*)(C + (size_t)(row0 + 8) * Ntot + col0) = v1;
        }
    }
}

// ---------------- pre-pass: elementwise tf32 RNA rounding ----------------
__global__ void round_kernel(const float* __restrict__ in,
                             float* __restrict__ out, int n4) {
    int i = blockIdx.x * blockDim.x + threadIdx.x;
    if (i >= n4) return;
    float4 v = ((const float4*)in)[i];
    v.x = tf32_rna(v.x); v.y = tf32_rna(v.y);
    v.z = tf32_rna(v.z); v.w = tf32_rna(v.w);
    ((float4*)out)[i] = v;
}

// ---------------- fused LayerNorm + SiLU (+ tf32 rounding of h) -------------
__launch_bounds__(256)
__global__ void ln_silu_kernel(const float* __restrict__ ln_w,
                               const float* __restrict__ ln_b) {
    const int row = blockIdx.x;
    const int m   = row >> 12;
    float* hp = g_h + (size_t)row * H_DIM;
    const int t = threadIdx.x;

    float4 x = *(const float4*)(hp + t * 4);
    float s = x.x + x.y + x.z + x.w;
    float q = x.x * x.x + x.y * x.y + x.z * x.z + x.w * x.w;
#pragma unroll
    for (int o = 16; o; o >>= 1) {
        s += __shfl_xor_sync(0xffffffffu, s, o);
        q += __shfl_xor_sync(0xffffffffu, q, o);
    }
    __shared__ float rs[8], rq[8];
    if ((t & 31) == 0) { rs[t >> 5] = s; rq[t >> 5] = q; }
    __syncthreads();
    s = rs[0] + rs[1] + rs[2] + rs[3] + rs[4] + rs[5] + rs[6] + rs[7];
    q = rq[0] + rq[1] + rq[2] + rq[3] + rq[4] + rq[5] + rq[6] + rq[7];

    const float mu  = s * (1.0f / H_DIM);
    const float var = q * (1.0f / H_DIM) - mu * mu;
    const float inv = rsqrtf(var + 1e-5f);

    const float4 w = *(const float4*)(ln_w + (size_t)m * H_DIM + t * 4);
    const float4 b = *(const float4*)(ln_b + (size_t)m * H_DIM + t * 4);

    float4 y; float v;
    v = (x.x - mu) * inv * w.x + b.x; y.x = tf32_rna(v / (1.f + __expf(-v)));
    v = (x.y - mu) * inv * w.y + b.y; y.y = tf32_rna(v / (1.f + __expf(-v)));
    v = (x.z - mu) * inv * w.z + b.z; y.z = tf32_rna(v / (1.f + __expf(-v)));
    v = (x.w - mu) * inv * w.w + b.w; y.w = tf32_rna(v / (1.f + __expf(-v)));
    *(float4*)(hp + t * 4) = y;
}

// ---------------- launch ----------------
extern "C" void kernel_launch(void* const* d_in, const int* in_sizes, int n_in,
                              void* d_out, int out_size) {
    const float* x  = (const float*)d_in[0];
    const float* W1 = (const float*)d_in[1];
    const float* b1 = (const float*)d_in[2];
    const float* lw = (const float*)d_in[3];
    const float* lb = (const float*)d_in[4];
    const float* W2 = (const float*)d_in[5];
    const float* b2 = (const float*)d_in[6];
    float* out = (float*)d_out;

    float *xr, *w1r, *w2r, *h;
    cudaGetSymbolAddress((void**)&xr,  g_xr);
    cudaGetSymbolAddress((void**)&w1r, g_w1r);
    cudaGetSymbolAddress((void**)&w2r, g_w2r);
    cudaGetSymbolAddress((void**)&h,   g_h);

    cudaFuncSetAttribute(gemm_mma, cudaFuncAttributeMaxDynamicSharedMemorySize,
                         SMEM_TOTAL);

    // pre-pass: tf32 RNA rounding
    round_kernel<<<(ROWS * E_DIM / 4 + 511) / 512, 512>>>(x, xr,
                                                          ROWS * E_DIM / 4);
    round_kernel<<<(MEMB * E_DIM * H_DIM / 4 + 511) / 512, 512>>>(
        W1, w1r, MEMB * E_DIM * H_DIM / 4);
    round_kernel<<<(MEMB * H_DIM * V_DIM / 4 + 511) / 512, 512>>>(
        W2, w2r, MEMB * H_DIM * V_DIM / 4);

    // GEMM1: [32768,512] x [8: 512->1024] -> h (+b1)
    gemm_mma<<<dim3(H_DIM / BN, ROWS / BM), 256, SMEM_TOTAL>>>(
        xr, w1r, b1, h, E_DIM, H_DIM, E_DIM / BK);
    // LayerNorm + SiLU (+ tf32 rounding)
    ln_silu_kernel<<<ROWS, 256>>>(lw, lb);
    // GEMM2: [32768,1024] x [8: 1024->4096] -> out (+b2)
    gemm_mma<<<dim3(V_DIM / BN, ROWS / BM), 256, SMEM_TOTAL>>>(
        h, w2r, b2, out, H_DIM, V_DIM, H_DIM / BK);
}